// round 14
// baseline (speedup 1.0000x reference)
#include <cuda_runtime.h>
#include <cuda_bf16.h>
#include <cstdint>

// Problem constants (B=1, S=8192, D=1024, Hq=16, Hk=4, hd=64, W=512)
#define S_LEN   8192
#define D_MODEL 1024
#define QKV_N   1536
#define HQ      16
#define HK      4
#define HD      64
#define WIN     512
#define NB      16
#define KV_COL0 1024
#define KV_LD   512
#define GK      1024
#define FULLM   0xffffffffu

__device__ float g_qkv[(size_t)S_LEN * QKV_N];
__device__ float g_att[(size_t)S_LEN * D_MODEL];
__device__ float g_xr[(size_t)S_LEN * D_MODEL];
__device__ float g_wqkvr[(size_t)QKV_N * D_MODEL];
__device__ float g_wprojr[(size_t)D_MODEL * D_MODEL];

__device__ __forceinline__ uint32_t smem_u32(const void* p) {
    uint32_t a;
    asm("{ .reg .u64 t; cvta.to.shared.u64 t, %1; cvt.u32.u64 %0, t; }" : "=r"(a) : "l"(p));
    return a;
}
__device__ __forceinline__ uint32_t f2tf32(float x) {
    uint32_t u;
    asm("cvt.rna.tf32.f32 %0, %1;" : "=r"(u) : "f"(x));
    return u;
}
__device__ __forceinline__ float ex2f(float x) {
    float y;
    asm("ex2.approx.f32 %0, %1;" : "=f"(y) : "f"(x));
    return y;
}
__device__ __forceinline__ void mma_tf32(float c[4], const uint32_t a[4], uint32_t b0, uint32_t b1) {
    asm volatile(
        "mma.sync.aligned.m16n8k8.row.col.f32.tf32.tf32.f32 "
        "{%0,%1,%2,%3}, {%4,%5,%6,%7}, {%8,%9}, {%0,%1,%2,%3};"
        : "+f"(c[0]), "+f"(c[1]), "+f"(c[2]), "+f"(c[3])
        : "r"(a[0]), "r"(a[1]), "r"(a[2]), "r"(a[3]), "r"(b0), "r"(b1));
}
__device__ __forceinline__ void ldsm4(uint32_t& r0, uint32_t& r1, uint32_t& r2, uint32_t& r3, uint32_t a) {
    asm volatile("ldmatrix.sync.aligned.m8n8.x4.shared.b16 {%0,%1,%2,%3}, [%4];"
        : "=r"(r0), "=r"(r1), "=r"(r2), "=r"(r3) : "r"(a));
}

// ============================================================================
// Pre-round to tf32 (rna), elementwise, float4 granularity.
// ============================================================================
__global__ void __launch_bounds__(256) round_kernel(
    const float* __restrict__ src, float* __restrict__ dst, int n4)
{
    int i = blockIdx.x * blockDim.x + threadIdx.x;
    int stride = gridDim.x * blockDim.x;
    for (; i < n4; i += stride) {
        float4 v = reinterpret_cast<const float4*>(src)[i];
        v.x = __uint_as_float(f2tf32(v.x));
        v.y = __uint_as_float(f2tf32(v.y));
        v.z = __uint_as_float(f2tf32(v.z));
        v.w = __uint_as_float(f2tf32(v.w));
        reinterpret_cast<float4*>(dst)[i] = v;
    }
}

// ============================================================================
// tf32 mma.sync GEMM: CTA 128x128, 512 threads (16 warps, 4x4), warp 32x32.
// BK=32 chunks, 2-stage buffer, ONE barrier per chunk (32 total).
// Order per iter: wait_group 0 -> sync -> issue(kc+1) -> compute(kc).
// Inputs pre-rounded to tf32. Optional C2 gets cols >= c2_col0.
// ============================================================================
#define GST 36                       // smem row stride (floats): 32 data + 4 pad
#define STG_FL (128 * GST)           // 4608 floats per tensor per stage
#define STAGE_FL (2 * STG_FL)        // 9216
#define GEMM_SMEM (2 * STAGE_FL * 4) // 73728 bytes

__global__ void __launch_bounds__(512, 2) gemm_mma_kernel(
    const float* __restrict__ A, const float* __restrict__ B,
    float* __restrict__ C, float* __restrict__ C2,
    int N, int c2_col0, int c2_ld)
{
    extern __shared__ float gsm[];
    const uint32_t smb = smem_u32(gsm);

    const int tid = threadIdx.x;
    const int wid = tid >> 5, lane = tid & 31;
    const int g = lane >> 2, tg = lane & 3;
    const int lr = lane & 7, lm = lane >> 3;
    const int wm = (wid & 3) * 32;
    const int wn = (wid >> 2) * 32;
    const int bm = blockIdx.y * 128, bn = blockIdx.x * 128;

    const uint32_t aB0 = (uint32_t)(((wm + (lm & 1) * 8 + lr) * GST + (lm >> 1) * 4) * 4);
    const uint32_t bB0 = (uint32_t)(((wn + (lm >> 1) * 8 + lr) * GST + (lm & 1) * 4) * 4);

    float acc[2][4][4];
#pragma unroll
    for (int i = 0; i < 2; i++)
#pragma unroll
        for (int j = 0; j < 4; j++)
#pragma unroll
            for (int r = 0; r < 4; r++) acc[i][j][r] = 0.0f;

    // one chunk = 32 K-floats: A 128x32, B 128x32 -> 1024 float4 each
    auto issue = [&](int kc) {
        const int st = kc & 1;
        const uint32_t sa = smb + (uint32_t)st * STAGE_FL * 4;
        const uint32_t sb = sa + STG_FL * 4;
#pragma unroll
        for (int i = 0; i < 2; i++) {
            const int idx = tid + i * 512;       // 0..1023
            const int row = idx >> 3, q = idx & 7;
            const uint32_t sm = (uint32_t)(row * GST + q * 4) * 4;
            const float* ga = A + (size_t)(bm + row) * GK + kc * 32 + q * 4;
            asm volatile("cp.async.cg.shared.global [%0], [%1], 16;" :: "r"(sa + sm), "l"(ga));
            const float* gb = B + (size_t)(bn + row) * GK + kc * 32 + q * 4;
            asm volatile("cp.async.cg.shared.global [%0], [%1], 16;" :: "r"(sb + sm), "l"(gb));
        }
        asm volatile("cp.async.commit_group;" ::: "memory");
    };

    issue(0);

    const int NKC = GK / 32;   // 32
    for (int kc = 0; kc < NKC; kc++) {
        asm volatile("cp.async.wait_group 0;" ::: "memory");
        __syncthreads();
        if (kc + 1 < NKC) issue(kc + 1);

        const int st = kc & 1;
        const uint32_t sa = smb + (uint32_t)st * STAGE_FL * 4;
        const uint32_t sb = sa + STG_FL * 4;
#pragma unroll
        for (int ks = 0; ks < 4; ks++) {
            uint32_t af[2][4], bf[4][2];
#pragma unroll
            for (int im = 0; im < 2; im++)
                ldsm4(af[im][0], af[im][1], af[im][2], af[im][3],
                      sa + aB0 + (uint32_t)(im * 16 * GST * 4) + (uint32_t)(ks * 32));
#pragma unroll
            for (int inp = 0; inp < 2; inp++)
                ldsm4(bf[2 * inp][0], bf[2 * inp][1], bf[2 * inp + 1][0], bf[2 * inp + 1][1],
                      sb + bB0 + (uint32_t)(inp * 16 * GST * 4) + (uint32_t)(ks * 32));
#pragma unroll
            for (int im = 0; im < 2; im++)
#pragma unroll
                for (int in_ = 0; in_ < 4; in_++)
                    mma_tf32(acc[im][in_], af[im], bf[in_][0], bf[in_][1]);
        }
    }

    const bool kvt = (C2 != nullptr) && (bn >= c2_col0);
#pragma unroll
    for (int im = 0; im < 2; im++) {
        const int row0 = bm + wm + im * 16 + g;
#pragma unroll
        for (int in_ = 0; in_ < 4; in_++) {
            const int col = bn + wn + in_ * 8 + 2 * tg;
            float2 v0 = make_float2(acc[im][in_][0], acc[im][in_][1]);
            float2 v1 = make_float2(acc[im][in_][2], acc[im][in_][3]);
            *reinterpret_cast<float2*>(C + (size_t)row0 * N + col) = v0;
            *reinterpret_cast<float2*>(C + (size_t)(row0 + 8) * N + col) = v1;
            if (kvt) {
                const int c2c = col - c2_col0;
                *reinterpret_cast<float2*>(C2 + (size_t)row0 * c2_ld + c2c) = v0;
                *reinterpret_cast<float2*>(C2 + (size_t)(row0 + 8) * c2_ld + c2c) = v1;
            }
        }
    }
}

// ============================================================================
// Flash attention, mma.sync tf32, LDSM K fragments, smem P relayout,
// per-warp chunk skipping. Output stored pre-rounded to tf32. (unchanged)
// ============================================================================
#define KS_ST 68
#define VS_ST 72
#define PS_ST 68
#define KS_FL (64 * KS_ST)
#define VS_FL (64 * VS_ST)
#define P_FL  (16 * PS_ST)
#define ATT_SMEM ((2 * KS_FL + 2 * VS_FL + 8 * P_FL) * 4)   // 106496 bytes

__global__ void __launch_bounds__(256, 2) attn_mma_kernel(
    const float* __restrict__ qkv, float* __restrict__ att)
{
    extern __shared__ float sm[];
    const int qt = blockIdx.x, h = blockIdx.y, n = blockIdx.z, hk = h >> 2;
    const int tid = threadIdx.x, wid = tid >> 5, lane = tid & 31;
    const int g = lane >> 2, tg = lane & 3;
    const int lr = lane & 7, lm = lane >> 3;
    const int abase = qt * 128 + wid * 16;
    const int a0 = abase + g, a1 = a0 + 8;
    const float qscale = 0.125f * 1.44269504f;
    const float slope2 = exp2f(-0.5f * (float)(h + 1)) * 1.44269504f;
    const uint32_t smb = smem_u32(sm);
    const bool nz = (n > 0);

    const uint32_t pbase = smb + (uint32_t)(2 * KS_FL + 2 * VS_FL + wid * P_FL) * 4;
    const uint32_t kB0 = (uint32_t)((((lm >> 1) * 8 + lr) * KS_ST + (lm & 1) * 4) * 4);
    const uint32_t pB0 = (uint32_t)((((lm & 1) * 8 + lr) * PS_ST + (lm >> 1) * 4) * 4);

    const int jlo = (wid * 16 + 15 + 63) >> 6;
    const int jhi = (wid * 16 + 449) >> 6;

    uint32_t qf[8][4];
    {
        const float* q0 = qkv + (size_t)(n * WIN + a0) * QKV_N + h * HD;
        const float* q1 = qkv + (size_t)(n * WIN + a1) * QKV_N + h * HD;
#pragma unroll
        for (int kc = 0; kc < 8; kc++) {
            qf[kc][0] = f2tf32(q0[kc * 8 + tg] * qscale);
            qf[kc][1] = f2tf32(q1[kc * 8 + tg] * qscale);
            qf[kc][2] = f2tf32(q0[kc * 8 + tg + 4] * qscale);
            qf[kc][3] = f2tf32(q1[kc * 8 + tg + 4] * qscale);
        }
    }

    float o[8][4];
#pragma unroll
    for (int i = 0; i < 8; i++)
#pragma unroll
        for (int j = 0; j < 4; j++) o[i][j] = 0.0f;
    float m0 = -1e30f, m1 = -1e30f, l0 = 0.0f, l1 = 0.0f;

    auto issue = [&](int ci) {
        const int st = ci & 1;
        const uint32_t kbase = smb + (uint32_t)st * KS_FL * 4;
        const uint32_t vbase = smb + (uint32_t)(2 * KS_FL + st * VS_FL) * 4;
        const int u0 = ci * 64;
#pragma unroll
        for (int i = 0; i < 4; i++) {
            const int idx = tid + i * 256;
            const int r = idx >> 4, c4 = idx & 15;
            const int gk = (n - 1) * WIN + u0 + r;
            const int pr = (gk >= 0) ? 16 : 0;
            const size_t base = (size_t)(gk >= 0 ? gk : 0) * QKV_N;
            const float* ks = qkv + base + (HQ + hk) * HD + c4 * 4;
            const float* vs = qkv + base + (HQ + HK + hk) * HD + c4 * 4;
            const uint32_t kd = kbase + (uint32_t)(r * KS_ST + c4 * 4) * 4;
            const uint32_t vd = vbase + (uint32_t)(r * VS_ST + c4 * 4) * 4;
            asm volatile("cp.async.cg.shared.global [%0], [%1], 16, %2;" :: "r"(kd), "l"(ks), "r"(pr));
            asm volatile("cp.async.cg.shared.global [%0], [%1], 16, %2;" :: "r"(vd), "l"(vs), "r"(pr));
        }
        asm volatile("cp.async.commit_group;" ::: "memory");
    };

    const int c0 = qt * 2;
    issue(c0);
    issue(c0 + 1);

    for (int ci = c0; ci < c0 + 10; ci++) {
        const int st = ci & 1;
        if (ci == c0 + 9) asm volatile("cp.async.wait_group 0;" ::: "memory");
        else              asm volatile("cp.async.wait_group 1;" ::: "memory");
        __syncthreads();

        const int j = ci - c0;
        const bool skip = ((wid >= 4) && (j == 0)) || ((wid < 4) && (j == 9)) ||
                          (!nz && (j <= 7 - 2 * qt));
        if (!skip) {
            const uint32_t kstb = smb + (uint32_t)st * KS_FL * 4;
            const float* Vst = sm + 2 * KS_FL + st * VS_FL;
            const int u0 = ci * 64;
            const bool needmask = (j < jlo) || (j > jhi) || (!nz && (j < 8 - 2 * qt));

            float sacc[8][4];
#pragma unroll
            for (int nt = 0; nt < 8; nt++)
#pragma unroll
                for (int jj = 0; jj < 4; jj++) sacc[nt][jj] = 0.0f;

#pragma unroll
            for (int ntp = 0; ntp < 4; ntp++) {
#pragma unroll
                for (int kc = 0; kc < 8; kc++) {
                    uint32_t b00, b01, b10, b11;
                    ldsm4(b00, b01, b10, b11,
                          kstb + kB0 + (uint32_t)(ntp * 16 * KS_ST * 4) + (uint32_t)(kc * 32));
                    mma_tf32(sacc[2 * ntp], qf[kc], b00, b01);
                    mma_tf32(sacc[2 * ntp + 1], qf[kc], b10, b11);
                }
            }

            float mx0 = -1e30f, mx1 = -1e30f;
            if (needmask) {
#pragma unroll
                for (int nt = 0; nt < 8; nt++) {
                    const int ub = u0 + nt * 8 + 2 * tg;
#pragma unroll
                    for (int jj = 0; jj < 4; jj++) {
                        const int u = ub + (jj & 1);
                        const int a = (jj < 2) ? a0 : a1;
                        const int diff = a + WIN - u;
                        const bool ok = ((unsigned)diff <= (unsigned)WIN) && (nz || (u >= WIN));
                        float s = ok ? (sacc[nt][jj] + slope2 * (float)u) : -1e30f;
                        sacc[nt][jj] = s;
                        if (jj < 2) mx0 = fmaxf(mx0, s);
                        else        mx1 = fmaxf(mx1, s);
                    }
                }
            } else {
#pragma unroll
                for (int nt = 0; nt < 8; nt++) {
                    const int ub = u0 + nt * 8 + 2 * tg;
#pragma unroll
                    for (int jj = 0; jj < 4; jj++) {
                        const int u = ub + (jj & 1);
                        float s = sacc[nt][jj] + slope2 * (float)u;
                        sacc[nt][jj] = s;
                        if (jj < 2) mx0 = fmaxf(mx0, s);
                        else        mx1 = fmaxf(mx1, s);
                    }
                }
            }
            mx0 = fmaxf(mx0, __shfl_xor_sync(FULLM, mx0, 1));
            mx0 = fmaxf(mx0, __shfl_xor_sync(FULLM, mx0, 2));
            mx1 = fmaxf(mx1, __shfl_xor_sync(FULLM, mx1, 1));
            mx1 = fmaxf(mx1, __shfl_xor_sync(FULLM, mx1, 2));

            const float nm0 = fmaxf(m0, mx0), nm1 = fmaxf(m1, mx1);
            const float cr0 = ex2f(m0 - nm0), cr1 = ex2f(m1 - nm1);
            l0 *= cr0; l1 *= cr1; m0 = nm0; m1 = nm1;
#pragma unroll
            for (int nt = 0; nt < 8; nt++) {
                o[nt][0] *= cr0; o[nt][1] *= cr0;
                o[nt][2] *= cr1; o[nt][3] *= cr1;
            }

#pragma unroll
            for (int nt = 0; nt < 8; nt++) {
                float p0 = ex2f(sacc[nt][0] - nm0);
                float p1 = ex2f(sacc[nt][1] - nm0);
                float p2 = ex2f(sacc[nt][2] - nm1);
                float p3 = ex2f(sacc[nt][3] - nm1);
                if (needmask) {
                    p0 = (sacc[nt][0] < -5e29f) ? 0.0f : p0;
                    p1 = (sacc[nt][1] < -5e29f) ? 0.0f : p1;
                    p2 = (sacc[nt][2] < -5e29f) ? 0.0f : p2;
                    p3 = (sacc[nt][3] < -5e29f) ? 0.0f : p3;
                }
                l0 += p0 + p1; l1 += p2 + p3;
                const uint32_t col = (uint32_t)(nt * 8 + 2 * tg);
                uint32_t r0 = f2tf32(p0), r1 = f2tf32(p1), r2 = f2tf32(p2), r3 = f2tf32(p3);
                asm volatile("st.shared.v2.b32 [%0], {%1, %2};"
                             :: "r"(pbase + (g * PS_ST + col) * 4), "r"(r0), "r"(r1));
                asm volatile("st.shared.v2.b32 [%0], {%1, %2};"
                             :: "r"(pbase + ((g + 8) * PS_ST + col) * 4), "r"(r2), "r"(r3));
            }
            __syncwarp();

#pragma unroll
            for (int kc = 0; kc < 8; kc++) {
                uint32_t pa[4];
                ldsm4(pa[0], pa[1], pa[2], pa[3], pbase + pB0 + (uint32_t)(kc * 32));
                const float* vr0 = Vst + (kc * 8 + tg) * VS_ST;
                const float* vr1 = Vst + (kc * 8 + tg + 4) * VS_ST;
#pragma unroll
                for (int ntd = 0; ntd < 8; ntd++) {
                    uint32_t b0 = __float_as_uint(vr0[ntd * 8 + g]);
                    uint32_t b1 = __float_as_uint(vr1[ntd * 8 + g]);
                    mma_tf32(o[ntd], pa, b0, b1);
                }
            }
            __syncwarp();
        }

        __syncthreads();
        if (ci + 2 < c0 + 10) issue(ci + 2);
    }

    l0 += __shfl_xor_sync(FULLM, l0, 1);
    l0 += __shfl_xor_sync(FULLM, l0, 2);
    l1 += __shfl_xor_sync(FULLM, l1, 1);
    l1 += __shfl_xor_sync(FULLM, l1, 2);
    const float i0 = 1.0f / l0, i1 = 1.0f / l1;

    float* o0 = att + (size_t)(n * WIN + a0) * D_MODEL + h * HD;
    float* o1 = att + (size_t)(n * WIN + a1) * D_MODEL + h * HD;
#pragma unroll
    for (int ntd = 0; ntd < 8; ntd++) {
        const int d = ntd * 8 + 2 * tg;
        float2 v0, v1;
        v0.x = __uint_as_float(f2tf32(o[ntd][0] * i0));
        v0.y = __uint_as_float(f2tf32(o[ntd][1] * i0));
        v1.x = __uint_as_float(f2tf32(o[ntd][2] * i1));
        v1.y = __uint_as_float(f2tf32(o[ntd][3] * i1));
        *reinterpret_cast<float2*>(o0 + d) = v0;
        *reinterpret_cast<float2*>(o1 + d) = v1;
    }
}

// ============================================================================
// Host launcher
// ============================================================================
extern "C" void kernel_launch(void* const* d_in, const int* in_sizes, int n_in,
                              void* d_out, int out_size)
{
    const float* x     = (const float*)d_in[0];
    const float* Wqkv  = (const float*)d_in[1];
    const float* Wproj = (const float*)d_in[2];

    float* out = (float*)d_out;
    float* kv  = out + (size_t)S_LEN * D_MODEL;

    float *qkv = nullptr, *att = nullptr, *xr = nullptr, *wqkvr = nullptr, *wprojr = nullptr;
    cudaGetSymbolAddress((void**)&qkv, g_qkv);
    cudaGetSymbolAddress((void**)&att, g_att);
    cudaGetSymbolAddress((void**)&xr, g_xr);
    cudaGetSymbolAddress((void**)&wqkvr, g_wqkvr);
    cudaGetSymbolAddress((void**)&wprojr, g_wprojr);

    cudaFuncSetAttribute(gemm_mma_kernel,
                         cudaFuncAttributeMaxDynamicSharedMemorySize, GEMM_SMEM);
    cudaFuncSetAttribute(attn_mma_kernel,
                         cudaFuncAttributeMaxDynamicSharedMemorySize, ATT_SMEM);

    // 0) pre-round inputs to tf32
    round_kernel<<<1024, 256>>>(x, xr, (S_LEN * D_MODEL) / 4);
    round_kernel<<<512, 256>>>(Wqkv, wqkvr, (QKV_N * D_MODEL) / 4);
    round_kernel<<<512, 256>>>(Wproj, wprojr, (D_MODEL * D_MODEL) / 4);

    // 1) QKV GEMM: [8192,1536]; kv_cache slice fused
    gemm_mma_kernel<<<dim3(QKV_N / 128, S_LEN / 128), 512, GEMM_SMEM>>>(
        xr, wqkvr, qkv, kv, QKV_N, KV_COL0, KV_LD);

    // 2) sliding-window attention -> att [8192, 1024] (stored tf32-rounded)
    attn_mma_kernel<<<dim3(4, HQ, NB), 256, ATT_SMEM>>>(qkv, att);

    // 3) projection GEMM: out = att @ Wproj^T
    gemm_mma_kernel<<<dim3(D_MODEL / 128, S_LEN / 128), 512, GEMM_SMEM>>>(
        att, wprojr, out, nullptr, D_MODEL, 0, 0);
}

// round 15
// speedup vs baseline: 1.4250x; 1.4250x over previous
#include <cuda_runtime.h>
#include <cuda_bf16.h>
#include <cstdint>

// Problem constants (B=1, S=8192, D=1024, Hq=16, Hk=4, hd=64, W=512)
#define S_LEN   8192
#define D_MODEL 1024
#define QKV_N   1536
#define HQ      16
#define HK      4
#define HD      64
#define WIN     512
#define NB      16
#define KV_COL0 1024
#define KV_LD   512
#define GK      1024
#define FULLM   0xffffffffu

__device__ float g_qkv[(size_t)S_LEN * QKV_N];
__device__ float g_att[(size_t)S_LEN * D_MODEL];
__device__ float g_wqkvr[(size_t)QKV_N * D_MODEL];
__device__ float g_wprojr[(size_t)D_MODEL * D_MODEL];

__device__ __forceinline__ uint32_t smem_u32(const void* p) {
    uint32_t a;
    asm("{ .reg .u64 t; cvta.to.shared.u64 t, %1; cvt.u32.u64 %0, t; }" : "=r"(a) : "l"(p));
    return a;
}
__device__ __forceinline__ uint32_t f2tf32(float x) {
    uint32_t u;
    asm("cvt.rna.tf32.f32 %0, %1;" : "=r"(u) : "f"(x));
    return u;
}
__device__ __forceinline__ uint32_t u2tf32(uint32_t x) {
    uint32_t u;
    asm("cvt.rna.tf32.f32 %0, %1;" : "=r"(u) : "f"(__uint_as_float(x)));
    return u;
}
__device__ __forceinline__ float ex2f(float x) {
    float y;
    asm("ex2.approx.f32 %0, %1;" : "=f"(y) : "f"(x));
    return y;
}
__device__ __forceinline__ void mma_tf32(float c[4], const uint32_t a[4], uint32_t b0, uint32_t b1) {
    asm volatile(
        "mma.sync.aligned.m16n8k8.row.col.f32.tf32.tf32.f32 "
        "{%0,%1,%2,%3}, {%4,%5,%6,%7}, {%8,%9}, {%0,%1,%2,%3};"
        : "+f"(c[0]), "+f"(c[1]), "+f"(c[2]), "+f"(c[3])
        : "r"(a[0]), "r"(a[1]), "r"(a[2]), "r"(a[3]), "r"(b0), "r"(b1));
}
__device__ __forceinline__ void ldsm4(uint32_t& r0, uint32_t& r1, uint32_t& r2, uint32_t& r3, uint32_t a) {
    asm volatile("ldmatrix.sync.aligned.m8n8.x4.shared.b16 {%0,%1,%2,%3}, [%4];"
        : "=r"(r0), "=r"(r1), "=r"(r2), "=r"(r3) : "r"(a));
}

// ============================================================================
// Pre-round to tf32 (rna), elementwise, float4 granularity (weights only).
// ============================================================================
__global__ void __launch_bounds__(256) round_kernel(
    const float* __restrict__ src, float* __restrict__ dst, int n4)
{
    int i = blockIdx.x * blockDim.x + threadIdx.x;
    int stride = gridDim.x * blockDim.x;
    for (; i < n4; i += stride) {
        float4 v = reinterpret_cast<const float4*>(src)[i];
        v.x = __uint_as_float(f2tf32(v.x));
        v.y = __uint_as_float(f2tf32(v.y));
        v.z = __uint_as_float(f2tf32(v.z));
        v.w = __uint_as_float(f2tf32(v.w));
        reinterpret_cast<float4*>(dst)[i] = v;
    }
}

// ============================================================================
// tf32 mma.sync GEMM (R8 shape): CTA 128x128, 512 threads (16 warps, 4x4),
// warp 32x32, BK=16, 3-stage cp.async pipeline, ldmatrix fragments.
// CVTA: round A fragments in-register (A may be raw f32). B must be
// pre-rounded to tf32. Optional C2 gets cols >= c2_col0 (kv_cache slice).
// ============================================================================
#define GST 20                      // smem row stride (floats) — LDSM conflict-free
#define STG_FL (128 * GST)          // 2560 floats per tensor per stage
#define STAGE_FL (2 * STG_FL)       // 5120
#define GEMM_SMEM (3 * STAGE_FL * 4)  // 61440 bytes

template<bool CVTA>
__global__ void __launch_bounds__(512, 2) gemm_mma_kernel(
    const float* __restrict__ A, const float* __restrict__ B,
    float* __restrict__ C, float* __restrict__ C2,
    int N, int c2_col0, int c2_ld)
{
    extern __shared__ float gsm[];
    const uint32_t smb = smem_u32(gsm);

    const int tid = threadIdx.x;
    const int wid = tid >> 5, lane = tid & 31;
    const int g = lane >> 2, tg = lane & 3;
    const int lr = lane & 7, lm = lane >> 3;
    const int wm = (wid & 3) * 32;
    const int wn = (wid >> 2) * 32;
    const int bm = blockIdx.y * 128, bn = blockIdx.x * 128;

    const uint32_t aB0 = (uint32_t)(((wm + (lm & 1) * 8 + lr) * GST + (lm >> 1) * 4) * 4);
    const uint32_t bB0 = (uint32_t)(((wn + (lm >> 1) * 8 + lr) * GST + (lm & 1) * 4) * 4);

    float acc[2][4][4];
#pragma unroll
    for (int i = 0; i < 2; i++)
#pragma unroll
        for (int j = 0; j < 4; j++)
#pragma unroll
            for (int r = 0; r < 4; r++) acc[i][j][r] = 0.0f;

    auto issue = [&](int kc) {
        const int st = kc % 3;
        const uint32_t sa = smb + (uint32_t)st * STAGE_FL * 4;
        const uint32_t sb = sa + STG_FL * 4;
        const int row = tid >> 2, q = tid & 3;
        const uint32_t sm = (uint32_t)(row * GST + q * 4) * 4;
        const float* ga = A + (size_t)(bm + row) * GK + kc * 16 + q * 4;
        asm volatile("cp.async.cg.shared.global [%0], [%1], 16;" :: "r"(sa + sm), "l"(ga));
        const float* gb = B + (size_t)(bn + row) * GK + kc * 16 + q * 4;
        asm volatile("cp.async.cg.shared.global [%0], [%1], 16;" :: "r"(sb + sm), "l"(gb));
        asm volatile("cp.async.commit_group;" ::: "memory");
    };

    issue(0); issue(1);

    const int NKC = GK / 16;   // 64
    for (int kc = 0; kc < NKC; kc++) {
        if (kc < NKC - 1) asm volatile("cp.async.wait_group 1;" ::: "memory");
        else              asm volatile("cp.async.wait_group 0;" ::: "memory");
        __syncthreads();
        if (kc + 2 < NKC) issue(kc + 2);

        const int st = kc % 3;
        const uint32_t sa = smb + (uint32_t)st * STAGE_FL * 4;
        const uint32_t sb = sa + STG_FL * 4;
#pragma unroll
        for (int ks = 0; ks < 2; ks++) {
            uint32_t af[2][4], bf[4][2];
#pragma unroll
            for (int im = 0; im < 2; im++) {
                ldsm4(af[im][0], af[im][1], af[im][2], af[im][3],
                      sa + aB0 + (uint32_t)(im * 16 * GST * 4) + (uint32_t)(ks * 32));
                if (CVTA) {
#pragma unroll
                    for (int r = 0; r < 4; r++) af[im][r] = u2tf32(af[im][r]);
                }
            }
#pragma unroll
            for (int inp = 0; inp < 2; inp++)
                ldsm4(bf[2 * inp][0], bf[2 * inp][1], bf[2 * inp + 1][0], bf[2 * inp + 1][1],
                      sb + bB0 + (uint32_t)(inp * 16 * GST * 4) + (uint32_t)(ks * 32));
#pragma unroll
            for (int im = 0; im < 2; im++)
#pragma unroll
                for (int in_ = 0; in_ < 4; in_++)
                    mma_tf32(acc[im][in_], af[im], bf[in_][0], bf[in_][1]);
        }
    }

    const bool kvt = (C2 != nullptr) && (bn >= c2_col0);
#pragma unroll
    for (int im = 0; im < 2; im++) {
        const int row0 = bm + wm + im * 16 + g;
#pragma unroll
        for (int in_ = 0; in_ < 4; in_++) {
            const int col = bn + wn + in_ * 8 + 2 * tg;
            float2 v0 = make_float2(acc[im][in_][0], acc[im][in_][1]);
            float2 v1 = make_float2(acc[im][in_][2], acc[im][in_][3]);
            *reinterpret_cast<float2*>(C + (size_t)row0 * N + col) = v0;
            *reinterpret_cast<float2*>(C + (size_t)(row0 + 8) * N + col) = v1;
            if (kvt) {
                const int c2c = col - c2_col0;
                *reinterpret_cast<float2*>(C2 + (size_t)row0 * c2_ld + c2c) = v0;
                *reinterpret_cast<float2*>(C2 + (size_t)(row0 + 8) * c2_ld + c2c) = v1;
            }
        }
    }
}

// ============================================================================
// Flash attention, mma.sync tf32, LDSM K fragments, smem P relayout,
// per-warp chunk skipping. Output stored pre-rounded to tf32. (R8 version)
// ============================================================================
#define KS_ST 68
#define VS_ST 72
#define PS_ST 68
#define KS_FL (64 * KS_ST)
#define VS_FL (64 * VS_ST)
#define P_FL  (16 * PS_ST)
#define ATT_SMEM ((2 * KS_FL + 2 * VS_FL + 8 * P_FL) * 4)   // 106496 bytes

__global__ void __launch_bounds__(256, 2) attn_mma_kernel(
    const float* __restrict__ qkv, float* __restrict__ att)
{
    extern __shared__ float sm[];
    const int qt = blockIdx.x, h = blockIdx.y, n = blockIdx.z, hk = h >> 2;
    const int tid = threadIdx.x, wid = tid >> 5, lane = tid & 31;
    const int g = lane >> 2, tg = lane & 3;
    const int lr = lane & 7, lm = lane >> 3;
    const int abase = qt * 128 + wid * 16;
    const int a0 = abase + g, a1 = a0 + 8;
    const float qscale = 0.125f * 1.44269504f;
    const float slope2 = exp2f(-0.5f * (float)(h + 1)) * 1.44269504f;
    const uint32_t smb = smem_u32(sm);
    const bool nz = (n > 0);

    const uint32_t pbase = smb + (uint32_t)(2 * KS_FL + 2 * VS_FL + wid * P_FL) * 4;
    const uint32_t kB0 = (uint32_t)((((lm >> 1) * 8 + lr) * KS_ST + (lm & 1) * 4) * 4);
    const uint32_t pB0 = (uint32_t)((((lm & 1) * 8 + lr) * PS_ST + (lm >> 1) * 4) * 4);

    const int jlo = (wid * 16 + 15 + 63) >> 6;
    const int jhi = (wid * 16 + 449) >> 6;

    uint32_t qf[8][4];
    {
        const float* q0 = qkv + (size_t)(n * WIN + a0) * QKV_N + h * HD;
        const float* q1 = qkv + (size_t)(n * WIN + a1) * QKV_N + h * HD;
#pragma unroll
        for (int kc = 0; kc < 8; kc++) {
            qf[kc][0] = f2tf32(q0[kc * 8 + tg] * qscale);
            qf[kc][1] = f2tf32(q1[kc * 8 + tg] * qscale);
            qf[kc][2] = f2tf32(q0[kc * 8 + tg + 4] * qscale);
            qf[kc][3] = f2tf32(q1[kc * 8 + tg + 4] * qscale);
        }
    }

    float o[8][4];
#pragma unroll
    for (int i = 0; i < 8; i++)
#pragma unroll
        for (int j = 0; j < 4; j++) o[i][j] = 0.0f;
    float m0 = -1e30f, m1 = -1e30f, l0 = 0.0f, l1 = 0.0f;

    auto issue = [&](int ci) {
        const int st = ci & 1;
        const uint32_t kbase = smb + (uint32_t)st * KS_FL * 4;
        const uint32_t vbase = smb + (uint32_t)(2 * KS_FL + st * VS_FL) * 4;
        const int u0 = ci * 64;
#pragma unroll
        for (int i = 0; i < 4; i++) {
            const int idx = tid + i * 256;
            const int r = idx >> 4, c4 = idx & 15;
            const int gk = (n - 1) * WIN + u0 + r;
            const int pr = (gk >= 0) ? 16 : 0;
            const size_t base = (size_t)(gk >= 0 ? gk : 0) * QKV_N;
            const float* ks = qkv + base + (HQ + hk) * HD + c4 * 4;
            const float* vs = qkv + base + (HQ + HK + hk) * HD + c4 * 4;
            const uint32_t kd = kbase + (uint32_t)(r * KS_ST + c4 * 4) * 4;
            const uint32_t vd = vbase + (uint32_t)(r * VS_ST + c4 * 4) * 4;
            asm volatile("cp.async.cg.shared.global [%0], [%1], 16, %2;" :: "r"(kd), "l"(ks), "r"(pr));
            asm volatile("cp.async.cg.shared.global [%0], [%1], 16, %2;" :: "r"(vd), "l"(vs), "r"(pr));
        }
        asm volatile("cp.async.commit_group;" ::: "memory");
    };

    const int c0 = qt * 2;
    issue(c0);
    issue(c0 + 1);

    for (int ci = c0; ci < c0 + 10; ci++) {
        const int st = ci & 1;
        if (ci == c0 + 9) asm volatile("cp.async.wait_group 0;" ::: "memory");
        else              asm volatile("cp.async.wait_group 1;" ::: "memory");
        __syncthreads();

        const int j = ci - c0;
        const bool skip = ((wid >= 4) && (j == 0)) || ((wid < 4) && (j == 9)) ||
                          (!nz && (j <= 7 - 2 * qt));
        if (!skip) {
            const uint32_t kstb = smb + (uint32_t)st * KS_FL * 4;
            const float* Vst = sm + 2 * KS_FL + st * VS_FL;
            const int u0 = ci * 64;
            const bool needmask = (j < jlo) || (j > jhi) || (!nz && (j < 8 - 2 * qt));

            float sacc[8][4];
#pragma unroll
            for (int nt = 0; nt < 8; nt++)
#pragma unroll
                for (int jj = 0; jj < 4; jj++) sacc[nt][jj] = 0.0f;

#pragma unroll
            for (int ntp = 0; ntp < 4; ntp++) {
#pragma unroll
                for (int kc = 0; kc < 8; kc++) {
                    uint32_t b00, b01, b10, b11;
                    ldsm4(b00, b01, b10, b11,
                          kstb + kB0 + (uint32_t)(ntp * 16 * KS_ST * 4) + (uint32_t)(kc * 32));
                    mma_tf32(sacc[2 * ntp], qf[kc], b00, b01);
                    mma_tf32(sacc[2 * ntp + 1], qf[kc], b10, b11);
                }
            }

            float mx0 = -1e30f, mx1 = -1e30f;
            if (needmask) {
#pragma unroll
                for (int nt = 0; nt < 8; nt++) {
                    const int ub = u0 + nt * 8 + 2 * tg;
#pragma unroll
                    for (int jj = 0; jj < 4; jj++) {
                        const int u = ub + (jj & 1);
                        const int a = (jj < 2) ? a0 : a1;
                        const int diff = a + WIN - u;
                        const bool ok = ((unsigned)diff <= (unsigned)WIN) && (nz || (u >= WIN));
                        float s = ok ? (sacc[nt][jj] + slope2 * (float)u) : -1e30f;
                        sacc[nt][jj] = s;
                        if (jj < 2) mx0 = fmaxf(mx0, s);
                        else        mx1 = fmaxf(mx1, s);
                    }
                }
            } else {
#pragma unroll
                for (int nt = 0; nt < 8; nt++) {
                    const int ub = u0 + nt * 8 + 2 * tg;
#pragma unroll
                    for (int jj = 0; jj < 4; jj++) {
                        const int u = ub + (jj & 1);
                        float s = sacc[nt][jj] + slope2 * (float)u;
                        sacc[nt][jj] = s;
                        if (jj < 2) mx0 = fmaxf(mx0, s);
                        else        mx1 = fmaxf(mx1, s);
                    }
                }
            }
            mx0 = fmaxf(mx0, __shfl_xor_sync(FULLM, mx0, 1));
            mx0 = fmaxf(mx0, __shfl_xor_sync(FULLM, mx0, 2));
            mx1 = fmaxf(mx1, __shfl_xor_sync(FULLM, mx1, 1));
            mx1 = fmaxf(mx1, __shfl_xor_sync(FULLM, mx1, 2));

            const float nm0 = fmaxf(m0, mx0), nm1 = fmaxf(m1, mx1);
            const float cr0 = ex2f(m0 - nm0), cr1 = ex2f(m1 - nm1);
            l0 *= cr0; l1 *= cr1; m0 = nm0; m1 = nm1;
#pragma unroll
            for (int nt = 0; nt < 8; nt++) {
                o[nt][0] *= cr0; o[nt][1] *= cr0;
                o[nt][2] *= cr1; o[nt][3] *= cr1;
            }

#pragma unroll
            for (int nt = 0; nt < 8; nt++) {
                float p0 = ex2f(sacc[nt][0] - nm0);
                float p1 = ex2f(sacc[nt][1] - nm0);
                float p2 = ex2f(sacc[nt][2] - nm1);
                float p3 = ex2f(sacc[nt][3] - nm1);
                if (needmask) {
                    p0 = (sacc[nt][0] < -5e29f) ? 0.0f : p0;
                    p1 = (sacc[nt][1] < -5e29f) ? 0.0f : p1;
                    p2 = (sacc[nt][2] < -5e29f) ? 0.0f : p2;
                    p3 = (sacc[nt][3] < -5e29f) ? 0.0f : p3;
                }
                l0 += p0 + p1; l1 += p2 + p3;
                const uint32_t col = (uint32_t)(nt * 8 + 2 * tg);
                uint32_t r0 = f2tf32(p0), r1 = f2tf32(p1), r2 = f2tf32(p2), r3 = f2tf32(p3);
                asm volatile("st.shared.v2.b32 [%0], {%1, %2};"
                             :: "r"(pbase + (g * PS_ST + col) * 4), "r"(r0), "r"(r1));
                asm volatile("st.shared.v2.b32 [%0], {%1, %2};"
                             :: "r"(pbase + ((g + 8) * PS_ST + col) * 4), "r"(r2), "r"(r3));
            }
            __syncwarp();

#pragma unroll
            for (int kc = 0; kc < 8; kc++) {
                uint32_t pa[4];
                ldsm4(pa[0], pa[1], pa[2], pa[3], pbase + pB0 + (uint32_t)(kc * 32));
                const float* vr0 = Vst + (kc * 8 + tg) * VS_ST;
                const float* vr1 = Vst + (kc * 8 + tg + 4) * VS_ST;
#pragma unroll
                for (int ntd = 0; ntd < 8; ntd++) {
                    uint32_t b0 = __float_as_uint(vr0[ntd * 8 + g]);
                    uint32_t b1 = __float_as_uint(vr1[ntd * 8 + g]);
                    mma_tf32(o[ntd], pa, b0, b1);
                }
            }
            __syncwarp();
        }

        __syncthreads();
        if (ci + 2 < c0 + 10) issue(ci + 2);
    }

    l0 += __shfl_xor_sync(FULLM, l0, 1);
    l0 += __shfl_xor_sync(FULLM, l0, 2);
    l1 += __shfl_xor_sync(FULLM, l1, 1);
    l1 += __shfl_xor_sync(FULLM, l1, 2);
    const float i0 = 1.0f / l0, i1 = 1.0f / l1;

    float* o0 = att + (size_t)(n * WIN + a0) * D_MODEL + h * HD;
    float* o1 = att + (size_t)(n * WIN + a1) * D_MODEL + h * HD;
#pragma unroll
    for (int ntd = 0; ntd < 8; ntd++) {
        const int d = ntd * 8 + 2 * tg;
        float2 v0, v1;
        v0.x = __uint_as_float(f2tf32(o[ntd][0] * i0));
        v0.y = __uint_as_float(f2tf32(o[ntd][1] * i0));
        v1.x = __uint_as_float(f2tf32(o[ntd][2] * i1));
        v1.y = __uint_as_float(f2tf32(o[ntd][3] * i1));
        *reinterpret_cast<float2*>(o0 + d) = v0;
        *reinterpret_cast<float2*>(o1 + d) = v1;
    }
}

// ============================================================================
// Host launcher
// ============================================================================
extern "C" void kernel_launch(void* const* d_in, const int* in_sizes, int n_in,
                              void* d_out, int out_size)
{
    const float* x     = (const float*)d_in[0];
    const float* Wqkv  = (const float*)d_in[1];
    const float* Wproj = (const float*)d_in[2];

    float* out = (float*)d_out;
    float* kv  = out + (size_t)S_LEN * D_MODEL;

    float *qkv = nullptr, *att = nullptr, *wqkvr = nullptr, *wprojr = nullptr;
    cudaGetSymbolAddress((void**)&qkv, g_qkv);
    cudaGetSymbolAddress((void**)&att, g_att);
    cudaGetSymbolAddress((void**)&wqkvr, g_wqkvr);
    cudaGetSymbolAddress((void**)&wprojr, g_wprojr);

    cudaFuncSetAttribute(gemm_mma_kernel<true>,
                         cudaFuncAttributeMaxDynamicSharedMemorySize, GEMM_SMEM);
    cudaFuncSetAttribute(gemm_mma_kernel<false>,
                         cudaFuncAttributeMaxDynamicSharedMemorySize, GEMM_SMEM);
    cudaFuncSetAttribute(attn_mma_kernel,
                         cudaFuncAttributeMaxDynamicSharedMemorySize, ATT_SMEM);

    // 0) pre-round weights to tf32 (x is rounded in-kernel by GEMM1)
    round_kernel<<<512, 256>>>(Wqkv, wqkvr, (QKV_N * D_MODEL) / 4);
    round_kernel<<<512, 256>>>(Wproj, wprojr, (D_MODEL * D_MODEL) / 4);

    // 1) QKV GEMM (A = raw x, cvt in-register): [8192,1536]; kv_cache fused
    gemm_mma_kernel<true><<<dim3(QKV_N / 128, S_LEN / 128), 512, GEMM_SMEM>>>(
        x, wqkvr, qkv, kv, QKV_N, KV_COL0, KV_LD);

    // 2) sliding-window attention -> att [8192, 1024] (stored tf32-rounded)
    attn_mma_kernel<<<dim3(4, HQ, NB), 256, ATT_SMEM>>>(qkv, att);

    // 3) projection GEMM (A = att, already tf32): out = att @ Wproj^T
    gemm_mma_kernel<false><<<dim3(D_MODEL / 128, S_LEN / 128), 512, GEMM_SMEM>>>(
        att, wprojr, out, nullptr, D_MODEL, 0, 0);
}

// round 17
// speedup vs baseline: 1.4775x; 1.0368x over previous
#include <cuda_runtime.h>
#include <cuda_bf16.h>
#include <cstdint>

// Problem constants (B=1, S=8192, D=1024, Hq=16, Hk=4, hd=64, W=512)
#define S_LEN   8192
#define D_MODEL 1024
#define QKV_N   1536
#define HQ      16
#define HK      4
#define HD      64
#define WIN     512
#define NB      16
#define KV_COL0 1024
#define KV_LD   512
#define GK      1024
#define FULLM   0xffffffffu

__device__ float g_qkv[(size_t)S_LEN * QKV_N];
__device__ float g_att[(size_t)S_LEN * D_MODEL];
__device__ float g_xr[(size_t)S_LEN * D_MODEL];
__device__ float g_wqkvr[(size_t)QKV_N * D_MODEL];
__device__ float g_wprojr[(size_t)D_MODEL * D_MODEL];

__device__ __forceinline__ uint32_t smem_u32(const void* p) {
    uint32_t a;
    asm("{ .reg .u64 t; cvta.to.shared.u64 t, %1; cvt.u32.u64 %0, t; }" : "=r"(a) : "l"(p));
    return a;
}
__device__ __forceinline__ uint32_t f2tf32(float x) {
    uint32_t u;
    asm("cvt.rna.tf32.f32 %0, %1;" : "=r"(u) : "f"(x));
    return u;
}
__device__ __forceinline__ float ex2f(float x) {
    float y;
    asm("ex2.approx.f32 %0, %1;" : "=f"(y) : "f"(x));
    return y;
}
__device__ __forceinline__ void mma_tf32(float c[4], const uint32_t a[4], uint32_t b0, uint32_t b1) {
    asm volatile(
        "mma.sync.aligned.m16n8k8.row.col.f32.tf32.tf32.f32 "
        "{%0,%1,%2,%3}, {%4,%5,%6,%7}, {%8,%9}, {%0,%1,%2,%3};"
        : "+f"(c[0]), "+f"(c[1]), "+f"(c[2]), "+f"(c[3])
        : "r"(a[0]), "r"(a[1]), "r"(a[2]), "r"(a[3]), "r"(b0), "r"(b1));
}
__device__ __forceinline__ void ldsm4(uint32_t& r0, uint32_t& r1, uint32_t& r2, uint32_t& r3, uint32_t a) {
    asm volatile("ldmatrix.sync.aligned.m8n8.x4.shared.b16 {%0,%1,%2,%3}, [%4];"
        : "=r"(r0), "=r"(r1), "=r"(r2), "=r"(r3) : "r"(a));
}

// ============================================================================
// Pre-round to tf32 (rna), elementwise, float4 granularity.
// ============================================================================
__global__ void __launch_bounds__(256) round_kernel(
    const float* __restrict__ src, float* __restrict__ dst, int n4)
{
    int i = blockIdx.x * blockDim.x + threadIdx.x;
    int stride = gridDim.x * blockDim.x;
    for (; i < n4; i += stride) {
        float4 v = reinterpret_cast<const float4*>(src)[i];
        v.x = __uint_as_float(f2tf32(v.x));
        v.y = __uint_as_float(f2tf32(v.y));
        v.z = __uint_as_float(f2tf32(v.z));
        v.w = __uint_as_float(f2tf32(v.w));
        reinterpret_cast<float4*>(dst)[i] = v;
    }
}

// ============================================================================
// tf32 mma.sync GEMM (R8, best measured): CTA 128x128, 512 threads (16 warps,
// 4x4), warp 32x32, BK=16, 3-stage cp.async pipeline, ldmatrix fragments.
// Inputs pre-rounded to tf32. Optional C2 gets cols >= c2_col0.
// ============================================================================
#define GST 20                      // smem row stride (floats) — LDSM conflict-free
#define STG_FL (128 * GST)          // 2560 floats per tensor per stage
#define STAGE_FL (2 * STG_FL)       // 5120
#define GEMM_SMEM (3 * STAGE_FL * 4)  // 61440 bytes

__global__ void __launch_bounds__(512, 2) gemm_mma_kernel(
    const float* __restrict__ A, const float* __restrict__ B,
    float* __restrict__ C, float* __restrict__ C2,
    int N, int c2_col0, int c2_ld)
{
    extern __shared__ float gsm[];
    const uint32_t smb = smem_u32(gsm);

    const int tid = threadIdx.x;
    const int wid = tid >> 5, lane = tid & 31;
    const int g = lane >> 2, tg = lane & 3;
    const int lr = lane & 7, lm = lane >> 3;
    const int wm = (wid & 3) * 32;
    const int wn = (wid >> 2) * 32;
    const int bm = blockIdx.y * 128, bn = blockIdx.x * 128;

    const uint32_t aB0 = (uint32_t)(((wm + (lm & 1) * 8 + lr) * GST + (lm >> 1) * 4) * 4);
    const uint32_t bB0 = (uint32_t)(((wn + (lm >> 1) * 8 + lr) * GST + (lm & 1) * 4) * 4);

    float acc[2][4][4];
#pragma unroll
    for (int i = 0; i < 2; i++)
#pragma unroll
        for (int j = 0; j < 4; j++)
#pragma unroll
            for (int r = 0; r < 4; r++) acc[i][j][r] = 0.0f;

    auto issue = [&](int kc) {
        const int st = kc % 3;
        const uint32_t sa = smb + (uint32_t)st * STAGE_FL * 4;
        const uint32_t sb = sa + STG_FL * 4;
        const int row = tid >> 2, q = tid & 3;
        const uint32_t sm = (uint32_t)(row * GST + q * 4) * 4;
        const float* ga = A + (size_t)(bm + row) * GK + kc * 16 + q * 4;
        asm volatile("cp.async.cg.shared.global [%0], [%1], 16;" :: "r"(sa + sm), "l"(ga));
        const float* gb = B + (size_t)(bn + row) * GK + kc * 16 + q * 4;
        asm volatile("cp.async.cg.shared.global [%0], [%1], 16;" :: "r"(sb + sm), "l"(gb));
        asm volatile("cp.async.commit_group;" ::: "memory");
    };

    issue(0); issue(1);

    const int NKC = GK / 16;   // 64
    for (int kc = 0; kc < NKC; kc++) {
        if (kc < NKC - 1) asm volatile("cp.async.wait_group 1;" ::: "memory");
        else              asm volatile("cp.async.wait_group 0;" ::: "memory");
        __syncthreads();
        if (kc + 2 < NKC) issue(kc + 2);

        const int st = kc % 3;
        const uint32_t sa = smb + (uint32_t)st * STAGE_FL * 4;
        const uint32_t sb = sa + STG_FL * 4;
#pragma unroll
        for (int ks = 0; ks < 2; ks++) {
            uint32_t af[2][4], bf[4][2];
#pragma unroll
            for (int im = 0; im < 2; im++)
                ldsm4(af[im][0], af[im][1], af[im][2], af[im][3],
                      sa + aB0 + (uint32_t)(im * 16 * GST * 4) + (uint32_t)(ks * 32));
#pragma unroll
            for (int inp = 0; inp < 2; inp++)
                ldsm4(bf[2 * inp][0], bf[2 * inp][1], bf[2 * inp + 1][0], bf[2 * inp + 1][1],
                      sb + bB0 + (uint32_t)(inp * 16 * GST * 4) + (uint32_t)(ks * 32));
#pragma unroll
            for (int im = 0; im < 2; im++)
#pragma unroll
                for (int in_ = 0; in_ < 4; in_++)
                    mma_tf32(acc[im][in_], af[im], bf[in_][0], bf[in_][1]);
        }
    }

    const bool kvt = (C2 != nullptr) && (bn >= c2_col0);
#pragma unroll
    for (int im = 0; im < 2; im++) {
        const int row0 = bm + wm + im * 16 + g;
#pragma unroll
        for (int in_ = 0; in_ < 4; in_++) {
            const int col = bn + wn + in_ * 8 + 2 * tg;
            float2 v0 = make_float2(acc[im][in_][0], acc[im][in_][1]);
            float2 v1 = make_float2(acc[im][in_][2], acc[im][in_][3]);
            *reinterpret_cast<float2*>(C + (size_t)row0 * N + col) = v0;
            *reinterpret_cast<float2*>(C + (size_t)(row0 + 8) * N + col) = v1;
            if (kvt) {
                const int c2c = col - c2_col0;
                *reinterpret_cast<float2*>(C2 + (size_t)row0 * c2_ld + c2c) = v0;
                *reinterpret_cast<float2*>(C2 + (size_t)(row0 + 8) * c2_ld + c2c) = v1;
            }
        }
    }
}

// ============================================================================
// Flash attention, mma.sync tf32, LDSM K fragments, smem P relayout,
// per-warp chunk skipping. Incremental ALiBi bias on the no-mask path;
// issue phase gated off for globally-dead (zero-fill) chunks.
// Output stored pre-rounded to tf32.
// ============================================================================
#define KS_ST 68
#define VS_ST 72
#define PS_ST 68
#define KS_FL (64 * KS_ST)
#define VS_FL (64 * VS_ST)
#define P_FL  (16 * PS_ST)
#define ATT_SMEM ((2 * KS_FL + 2 * VS_FL + 8 * P_FL) * 4)   // 106496 bytes

__global__ void __launch_bounds__(256, 2) attn_mma_kernel(
    const float* __restrict__ qkv, float* __restrict__ att)
{
    extern __shared__ float sm[];
    const int qt = blockIdx.x, h = blockIdx.y, n = blockIdx.z, hk = h >> 2;
    const int tid = threadIdx.x, wid = tid >> 5, lane = tid & 31;
    const int g = lane >> 2, tg = lane & 3;
    const int lr = lane & 7, lm = lane >> 3;
    const int abase = qt * 128 + wid * 16;
    const int a0 = abase + g, a1 = a0 + 8;
    const float qscale = 0.125f * 1.44269504f;
    const float slope2 = exp2f(-0.5f * (float)(h + 1)) * 1.44269504f;
    const float slope8 = slope2 * 8.0f;
    const uint32_t smb = smem_u32(sm);
    const bool nz = (n > 0);

    const uint32_t pbase = smb + (uint32_t)(2 * KS_FL + 2 * VS_FL + wid * P_FL) * 4;
    const uint32_t kB0 = (uint32_t)((((lm >> 1) * 8 + lr) * KS_ST + (lm & 1) * 4) * 4);
    const uint32_t pB0 = (uint32_t)((((lm & 1) * 8 + lr) * PS_ST + (lm >> 1) * 4) * 4);

    const int jlo = (wid * 16 + 15 + 63) >> 6;
    const int jhi = (wid * 16 + 449) >> 6;

    uint32_t qf[8][4];
    {
        const float* q0 = qkv + (size_t)(n * WIN + a0) * QKV_N + h * HD;
        const float* q1 = qkv + (size_t)(n * WIN + a1) * QKV_N + h * HD;
#pragma unroll
        for (int kc = 0; kc < 8; kc++) {
            qf[kc][0] = f2tf32(q0[kc * 8 + tg] * qscale);
            qf[kc][1] = f2tf32(q1[kc * 8 + tg] * qscale);
            qf[kc][2] = f2tf32(q0[kc * 8 + tg + 4] * qscale);
            qf[kc][3] = f2tf32(q1[kc * 8 + tg + 4] * qscale);
        }
    }

    float o[8][4];
#pragma unroll
    for (int i = 0; i < 8; i++)
#pragma unroll
        for (int j = 0; j < 4; j++) o[i][j] = 0.0f;
    float m0 = -1e30f, m1 = -1e30f, l0 = 0.0f, l1 = 0.0f;

    const int c0 = qt * 2;

    auto issue = [&](int ci) {
        // globally-dead chunk (block 0, fully zero-filled & skipped by all
        // warps): emit only the commit so wait_group counts stay aligned.
        const bool gskip = (!nz) && ((ci - c0) <= 7 - 2 * qt);
        if (!gskip) {
            const int st = ci & 1;
            const uint32_t kbase = smb + (uint32_t)st * KS_FL * 4;
            const uint32_t vbase = smb + (uint32_t)(2 * KS_FL + st * VS_FL) * 4;
            const int u0 = ci * 64;
#pragma unroll
            for (int i = 0; i < 4; i++) {
                const int idx = tid + i * 256;
                const int r = idx >> 4, c4 = idx & 15;
                const int gk = (n - 1) * WIN + u0 + r;
                const int pr = (gk >= 0) ? 16 : 0;
                const size_t base = (size_t)(gk >= 0 ? gk : 0) * QKV_N;
                const float* ks = qkv + base + (HQ + hk) * HD + c4 * 4;
                const float* vs = qkv + base + (HQ + HK + hk) * HD + c4 * 4;
                const uint32_t kd = kbase + (uint32_t)(r * KS_ST + c4 * 4) * 4;
                const uint32_t vd = vbase + (uint32_t)(r * VS_ST + c4 * 4) * 4;
                asm volatile("cp.async.cg.shared.global [%0], [%1], 16, %2;" :: "r"(kd), "l"(ks), "r"(pr));
                asm volatile("cp.async.cg.shared.global [%0], [%1], 16, %2;" :: "r"(vd), "l"(vs), "r"(pr));
            }
        }
        asm volatile("cp.async.commit_group;" ::: "memory");
    };

    issue(c0);
    issue(c0 + 1);

    for (int ci = c0; ci < c0 + 10; ci++) {
        const int st = ci & 1;
        if (ci == c0 + 9) asm volatile("cp.async.wait_group 0;" ::: "memory");
        else              asm volatile("cp.async.wait_group 1;" ::: "memory");
        __syncthreads();

        const int j = ci - c0;
        const bool skip = ((wid >= 4) && (j == 0)) || ((wid < 4) && (j == 9)) ||
                          (!nz && (j <= 7 - 2 * qt));
        if (!skip) {
            const uint32_t kstb = smb + (uint32_t)st * KS_FL * 4;
            const float* Vst = sm + 2 * KS_FL + st * VS_FL;
            const int u0 = ci * 64;
            const bool needmask = (j < jlo) || (j > jhi) || (!nz && (j < 8 - 2 * qt));

            float sacc[8][4];
#pragma unroll
            for (int nt = 0; nt < 8; nt++)
#pragma unroll
                for (int jj = 0; jj < 4; jj++) sacc[nt][jj] = 0.0f;

#pragma unroll
            for (int ntp = 0; ntp < 4; ntp++) {
#pragma unroll
                for (int kc = 0; kc < 8; kc++) {
                    uint32_t b00, b01, b10, b11;
                    ldsm4(b00, b01, b10, b11,
                          kstb + kB0 + (uint32_t)(ntp * 16 * KS_ST * 4) + (uint32_t)(kc * 32));
                    mma_tf32(sacc[2 * ntp], qf[kc], b00, b01);
                    mma_tf32(sacc[2 * ntp + 1], qf[kc], b10, b11);
                }
            }

            float mx0 = -1e30f, mx1 = -1e30f;
            if (needmask) {
#pragma unroll
                for (int nt = 0; nt < 8; nt++) {
                    const int ub = u0 + nt * 8 + 2 * tg;
#pragma unroll
                    for (int jj = 0; jj < 4; jj++) {
                        const int u = ub + (jj & 1);
                        const int a = (jj < 2) ? a0 : a1;
                        const int diff = a + WIN - u;
                        const bool ok = ((unsigned)diff <= (unsigned)WIN) && (nz || (u >= WIN));
                        float s = ok ? (sacc[nt][jj] + slope2 * (float)u) : -1e30f;
                        sacc[nt][jj] = s;
                        if (jj < 2) mx0 = fmaxf(mx0, s);
                        else        mx1 = fmaxf(mx1, s);
                    }
                }
            } else {
                // incremental ALiBi bias: fb = slope2 * u for the even column,
                // +slope2 for the odd column; advance by slope2*8 per n-tile.
                float fb = slope2 * (float)(u0 + 2 * tg);
#pragma unroll
                for (int nt = 0; nt < 8; nt++) {
                    const float b1 = fb + slope2;
                    float s;
                    s = sacc[nt][0] + fb; sacc[nt][0] = s; mx0 = fmaxf(mx0, s);
                    s = sacc[nt][1] + b1; sacc[nt][1] = s; mx0 = fmaxf(mx0, s);
                    s = sacc[nt][2] + fb; sacc[nt][2] = s; mx1 = fmaxf(mx1, s);
                    s = sacc[nt][3] + b1; sacc[nt][3] = s; mx1 = fmaxf(mx1, s);
                    fb += slope8;
                }
            }
            mx0 = fmaxf(mx0, __shfl_xor_sync(FULLM, mx0, 1));
            mx0 = fmaxf(mx0, __shfl_xor_sync(FULLM, mx0, 2));
            mx1 = fmaxf(mx1, __shfl_xor_sync(FULLM, mx1, 1));
            mx1 = fmaxf(mx1, __shfl_xor_sync(FULLM, mx1, 2));

            const float nm0 = fmaxf(m0, mx0), nm1 = fmaxf(m1, mx1);
            const float cr0 = ex2f(m0 - nm0), cr1 = ex2f(m1 - nm1);
            l0 *= cr0; l1 *= cr1; m0 = nm0; m1 = nm1;
#pragma unroll
            for (int nt = 0; nt < 8; nt++) {
                o[nt][0] *= cr0; o[nt][1] *= cr0;
                o[nt][2] *= cr1; o[nt][3] *= cr1;
            }

#pragma unroll
            for (int nt = 0; nt < 8; nt++) {
                float p0 = ex2f(sacc[nt][0] - nm0);
                float p1 = ex2f(sacc[nt][1] - nm0);
                float p2 = ex2f(sacc[nt][2] - nm1);
                float p3 = ex2f(sacc[nt][3] - nm1);
                if (needmask) {
                    p0 = (sacc[nt][0] < -5e29f) ? 0.0f : p0;
                    p1 = (sacc[nt][1] < -5e29f) ? 0.0f : p1;
                    p2 = (sacc[nt][2] < -5e29f) ? 0.0f : p2;
                    p3 = (sacc[nt][3] < -5e29f) ? 0.0f : p3;
                }
                l0 += p0 + p1; l1 += p2 + p3;
                const uint32_t col = (uint32_t)(nt * 8 + 2 * tg);
                uint32_t r0 = f2tf32(p0), r1 = f2tf32(p1), r2 = f2tf32(p2), r3 = f2tf32(p3);
                asm volatile("st.shared.v2.b32 [%0], {%1, %2};"
                             :: "r"(pbase + (g * PS_ST + col) * 4), "r"(r0), "r"(r1));
                asm volatile("st.shared.v2.b32 [%0], {%1, %2};"
                             :: "r"(pbase + ((g + 8) * PS_ST + col) * 4), "r"(r2), "r"(r3));
            }
            __syncwarp();

#pragma unroll
            for (int kc = 0; kc < 8; kc++) {
                uint32_t pa[4];
                ldsm4(pa[0], pa[1], pa[2], pa[3], pbase + pB0 + (uint32_t)(kc * 32));
                const float* vr0 = Vst + (kc * 8 + tg) * VS_ST;
                const float* vr1 = Vst + (kc * 8 + tg + 4) * VS_ST;
#pragma unroll
                for (int ntd = 0; ntd < 8; ntd++) {
                    uint32_t b0 = __float_as_uint(vr0[ntd * 8 + g]);
                    uint32_t b1 = __float_as_uint(vr1[ntd * 8 + g]);
                    mma_tf32(o[ntd], pa, b0, b1);
                }
            }
            __syncwarp();
        }

        __syncthreads();
        if (ci + 2 < c0 + 10) issue(ci + 2);
    }

    l0 += __shfl_xor_sync(FULLM, l0, 1);
    l0 += __shfl_xor_sync(FULLM, l0, 2);
    l1 += __shfl_xor_sync(FULLM, l1, 1);
    l1 += __shfl_xor_sync(FULLM, l1, 2);
    const float i0 = 1.0f / l0, i1 = 1.0f / l1;

    float* o0 = att + (size_t)(n * WIN + a0) * D_MODEL + h * HD;
    float* o1 = att + (size_t)(n * WIN + a1) * D_MODEL + h * HD;
#pragma unroll
    for (int ntd = 0; ntd < 8; ntd++) {
        const int d = ntd * 8 + 2 * tg;
        float2 v0, v1;
        v0.x = __uint_as_float(f2tf32(o[ntd][0] * i0));
        v0.y = __uint_as_float(f2tf32(o[ntd][1] * i0));
        v1.x = __uint_as_float(f2tf32(o[ntd][2] * i1));
        v1.y = __uint_as_float(f2tf32(o[ntd][3] * i1));
        *reinterpret_cast<float2*>(o0 + d) = v0;
        *reinterpret_cast<float2*>(o1 + d) = v1;
    }
}

// ============================================================================
// Host launcher
// ============================================================================
extern "C" void kernel_launch(void* const* d_in, const int* in_sizes, int n_in,
                              void* d_out, int out_size)
{
    const float* x     = (const float*)d_in[0];
    const float* Wqkv  = (const float*)d_in[1];
    const float* Wproj = (const float*)d_in[2];

    float* out = (float*)d_out;
    float* kv  = out + (size_t)S_LEN * D_MODEL;

    float *qkv = nullptr, *att = nullptr, *xr = nullptr, *wqkvr = nullptr, *wprojr = nullptr;
    cudaGetSymbolAddress((void**)&qkv, g_qkv);
    cudaGetSymbolAddress((void**)&att, g_att);
    cudaGetSymbolAddress((void**)&xr, g_xr);
    cudaGetSymbolAddress((void**)&wqkvr, g_wqkvr);
    cudaGetSymbolAddress((void**)&wprojr, g_wprojr);

    cudaFuncSetAttribute(gemm_mma_kernel,
                         cudaFuncAttributeMaxDynamicSharedMemorySize, GEMM_SMEM);
    cudaFuncSetAttribute(attn_mma_kernel,
                         cudaFuncAttributeMaxDynamicSharedMemorySize, ATT_SMEM);

    // 0) pre-round inputs to tf32
    round_kernel<<<1024, 256>>>(x, xr, (S_LEN * D_MODEL) / 4);
    round_kernel<<<512, 256>>>(Wqkv, wqkvr, (QKV_N * D_MODEL) / 4);
    round_kernel<<<512, 256>>>(Wproj, wprojr, (D_MODEL * D_MODEL) / 4);

    // 1) QKV GEMM: [8192,1536]; kv_cache slice fused
    gemm_mma_kernel<<<dim3(QKV_N / 128, S_LEN / 128), 512, GEMM_SMEM>>>(
        xr, wqkvr, qkv, kv, QKV_N, KV_COL0, KV_LD);

    // 2) sliding-window attention -> att [8192, 1024] (stored tf32-rounded)
    attn_mma_kernel<<<dim3(4, HQ, NB), 256, ATT_SMEM>>>(qkv, att);

    // 3) projection GEMM: out = att @ Wproj^T
    gemm_mma_kernel<<<dim3(D_MODEL / 128, S_LEN / 128), 512, GEMM_SMEM>>>(
        att, wprojr, out, nullptr, D_MODEL, 0, 0);
}